// round 13
// baseline (speedup 1.0000x reference)
#include <cuda_runtime.h>
#include <cuda_fp16.h>
#include <math.h>
#include <stdint.h>

#define B_ 4
#define N_ 2048
#define E_ 256
#define H_ 8
#define D_ 32
#define M_ (B_*N_)
// 1/sqrt(256) * log2(e): S computed in log2 domain, scale folded into Wq
#define QSCALE_ 0.09016844f

// Scratch
__device__ __half g_xh[M_*E_];
__device__ __half g_wh[4*E_*E_];
__device__ __half g_q[B_*H_*N_*D_];
__device__ __half g_k[B_*H_*N_*D_];
__device__ __half g_v[B_*H_*N_*D_];
__device__ __half g_oh[M_*E_];

// ---------------------------------------------------------------------------
// helpers
// ---------------------------------------------------------------------------
__device__ __forceinline__ void mma_f16(float c[4], const uint32_t a[4],
                                        uint32_t b0, uint32_t b1) {
    asm("mma.sync.aligned.m16n8k16.row.col.f32.f16.f16.f32 "
        "{%0,%1,%2,%3}, {%4,%5,%6,%7}, {%8,%9}, {%0,%1,%2,%3};"
        : "+f"(c[0]), "+f"(c[1]), "+f"(c[2]), "+f"(c[3])
        : "r"(a[0]), "r"(a[1]), "r"(a[2]), "r"(a[3]), "r"(b0), "r"(b1));
}
__device__ __forceinline__ void mma_f16c16(uint32_t c[2], const uint32_t a[4],
                                           uint32_t b0, uint32_t b1) {
    asm("mma.sync.aligned.m16n8k16.row.col.f16.f16.f16.f16 "
        "{%0,%1}, {%2,%3,%4,%5}, {%6,%7}, {%0,%1};"
        : "+r"(c[0]), "+r"(c[1])
        : "r"(a[0]), "r"(a[1]), "r"(a[2]), "r"(a[3]), "r"(b0), "r"(b1));
}
__device__ __forceinline__ uint32_t smem_u32(const void* p) {
    uint32_t a;
    asm("{ .reg .u64 t; cvta.to.shared.u64 t, %1; cvt.u32.u64 %0, t; }" : "=r"(a) : "l"(p));
    return a;
}
__device__ __forceinline__ uint32_t ex2h2(uint32_t x) {
    uint32_t r;
    asm("ex2.approx.f16x2 %0, %1;" : "=r"(r) : "r"(x));
    return r;
}
#define LDMX4(r0,r1,r2,r3,addr) \
    asm volatile("ldmatrix.sync.aligned.m8n8.x4.shared.b16 {%0,%1,%2,%3}, [%4];" \
        : "=r"(r0),"=r"(r1),"=r"(r2),"=r"(r3) : "r"(addr))
#define LDMX4T(r0,r1,r2,r3,addr) \
    asm volatile("ldmatrix.sync.aligned.m8n8.x4.trans.shared.b16 {%0,%1,%2,%3}, [%4];" \
        : "=r"(r0),"=r"(r1),"=r"(r2),"=r"(r3) : "r"(addr))
#define CP16(dst, src) \
    asm volatile("cp.async.cg.shared.global [%0], [%1], 16;" :: "r"(dst), "l"(src))
#define CP_COMMIT() asm volatile("cp.async.commit_group;" ::: "memory")
#define CP_WAIT0()  asm volatile("cp.async.wait_group 0;" ::: "memory")

// GEMM tile: 64x64 block, BK=64, stride 72 halfs (144B = 9*16B -> odd 16B
// multiple per row => conflict-free ldmatrix row addressing)
#define GK   64
#define GSTR 72
#define GBUF (64 * GSTR * 2)   // bytes per tile buffer

// ---------------------------------------------------------------------------
// Convert: x -> fp16, four W -> fp16 (Wq scaled by QSCALE_).
// ---------------------------------------------------------------------------
__global__ __launch_bounds__(256)
void convert_kernel(const float* __restrict__ x,
                    const float* __restrict__ Wq, const float* __restrict__ Wk,
                    const float* __restrict__ Wv, const float* __restrict__ Wo)
{
    const int bid = blockIdx.x;
    const int tid = threadIdx.x;
    const float* src;
    __half* dst;
    int idx;
    float sc = 1.f;
    if (bid < 2048) {
        idx = bid * 256 + tid;
        src = x; dst = g_xh;
    } else {
        int r = bid - 2048;
        int wsel = r >> 6;
        idx = (r & 63) * 256 + tid;
        src = (wsel == 0) ? Wq : (wsel == 1) ? Wk : (wsel == 2) ? Wv : Wo;
        dst = g_wh + (size_t)wsel * E_ * E_;
        if (wsel == 0) sc = QSCALE_;
    }
    float4 v = ((const float4*)src)[idx];
    ((__half2*)dst)[idx * 2]     = __floats2half2_rn(v.x * sc, v.y * sc);
    ((__half2*)dst)[idx * 2 + 1] = __floats2half2_rn(v.z * sc, v.w * sc);
}

// ---------------------------------------------------------------------------
// Fused QKV GEMM: block 64x64, BK=64, double-buffered single-sync cp.async.
// 8 warps (2m x 4n), warp tile 32x16. Static smem 36.9KB.
// grid (12, 128): blockIdx.x = wsel*4 + n-block, blockIdx.y = m-block.
// ---------------------------------------------------------------------------
__global__ __launch_bounds__(256)
void gemm_qkv(const float* __restrict__ bq, const float* __restrict__ bk,
              const float* __restrict__ bv)
{
    __shared__ __half Ah[2][64][GSTR];
    __shared__ __half Wh[2][64][GSTR];

    const int tid  = threadIdx.x;
    const int w    = tid >> 5;
    const int lane = tid & 31;
    const int g    = lane >> 2;
    const int q    = lane & 3;
    const int grp  = lane >> 3;
    const int lrow = lane & 7;
    const int warp_m = (w & 1) * 32;
    const int warp_n = (w >> 1) * 16;

    const int wsel = blockIdx.x >> 2;
    const int nBlock = (blockIdx.x & 3) * 64;
    const int mBlock = blockIdx.y * 64;
    const float* bias = (wsel == 0) ? bq : (wsel == 1) ? bk : bv;
    const float bsc = (wsel == 0) ? QSCALE_ : 1.f;
    __half* C = (wsel == 0) ? g_q : (wsel == 1) ? g_k : g_v;
    const __half* A  = g_xh;
    const __half* Wp = g_wh + (size_t)wsel * E_ * E_;

    // fill slots: tile = 64 rows x 8 chunks = 512 chunks; 2 per thread
    const int fr0 = tid >> 3,          fc = (tid & 7) * 8;
    const int fr1 = (tid + 256) >> 3;
    const uint32_t ad0 = smem_u32(&Ah[0][fr0][fc]);
    const uint32_t ad1 = smem_u32(&Ah[0][fr1][fc]);
    const uint32_t wd0 = smem_u32(&Wh[0][fr0][fc]);
    const uint32_t wd1 = smem_u32(&Wh[0][fr1][fc]);
    const __half* as0 = A  + (size_t)(mBlock + fr0) * E_ + fc;
    const __half* as1 = A  + (size_t)(mBlock + fr1) * E_ + fc;
    const __half* ws0 = Wp + (size_t)(nBlock + fr0) * E_ + fc;
    const __half* ws1 = Wp + (size_t)(nBlock + fr1) * E_ + fc;

    uint32_t abase[2];
    #pragma unroll
    for (int mt = 0; mt < 2; mt++)
        abase[mt] = smem_u32(&Ah[0][warp_m + mt * 16 + (grp & 1) * 8 + lrow][(grp >> 1) * 8]);
    const uint32_t wbase = smem_u32(&Wh[0][warp_n + (grp >> 1) * 8 + lrow][(grp & 1) * 8]);

    float acc[2][2][4];
    #pragma unroll
    for (int mt = 0; mt < 2; mt++)
        #pragma unroll
        for (int nt = 0; nt < 2; nt++)
            #pragma unroll
            for (int j = 0; j < 4; j++) acc[mt][nt][j] = 0.f;

    // preload k-tile 0
    CP16(ad0, as0); CP16(ad1, as1);
    CP16(wd0, ws0); CP16(wd1, ws1);
    CP_COMMIT();

    #pragma unroll
    for (int kt = 0; kt < E_ / GK; kt++) {
        const uint32_t cur = (kt & 1) * GBUF;
        CP_WAIT0();
        __syncthreads();
        if (kt + 1 < E_ / GK) {
            const int k0n = (kt + 1) * GK;
            const uint32_t nb = ((kt + 1) & 1) * GBUF;
            CP16(ad0 + nb, as0 + k0n); CP16(ad1 + nb, as1 + k0n);
            CP16(wd0 + nb, ws0 + k0n); CP16(wd1 + nb, ws1 + k0n);
            CP_COMMIT();
        }
        #pragma unroll
        for (int ks = 0; ks < GK / 16; ks++) {
            uint32_t af[2][4];
            #pragma unroll
            for (int mt = 0; mt < 2; mt++)
                LDMX4(af[mt][0], af[mt][1], af[mt][2], af[mt][3],
                      abase[mt] + cur + ks * 32);
            uint32_t b0, b1, b2, b3;
            LDMX4(b0, b1, b2, b3, wbase + cur + ks * 32);
            #pragma unroll
            for (int mt = 0; mt < 2; mt++) {
                mma_f16(acc[mt][0], af[mt], b0, b1);
                mma_f16(acc[mt][1], af[mt], b2, b3);
            }
        }
    }

    #pragma unroll
    for (int mt = 0; mt < 2; mt++) {
        int row0 = mBlock + warp_m + mt * 16 + g;
        #pragma unroll
        for (int nt = 0; nt < 2; nt++) {
            int e = nBlock + warp_n + nt * 8 + 2 * q;
            float be0 = bias[e] * bsc, be1 = bias[e + 1] * bsc;
            int h = e >> 5, dd = e & 31;
            int b0i = row0 / N_, n0 = row0 % N_;
            int b1i = (row0 + 8) / N_, n1 = (row0 + 8) % N_;
            __half2 h0 = __floats2half2_rn(acc[mt][nt][0] + be0, acc[mt][nt][1] + be1);
            __half2 h1 = __floats2half2_rn(acc[mt][nt][2] + be0, acc[mt][nt][3] + be1);
            *(__half2*)&C[(((size_t)b0i * H_ + h) * N_ + n0) * D_ + dd] = h0;
            *(__half2*)&C[(((size_t)b1i * H_ + h) * N_ + n1) * D_ + dd] = h1;
        }
    }
}

// ---------------------------------------------------------------------------
// Output projection: same 64x64xBK64 template, fp32 out. grid (4, 128).
// ---------------------------------------------------------------------------
__global__ __launch_bounds__(256)
void gemm_out(const float* __restrict__ bo, float* __restrict__ out)
{
    __shared__ __half Ah[2][64][GSTR];
    __shared__ __half Wh[2][64][GSTR];

    const int tid  = threadIdx.x;
    const int w    = tid >> 5;
    const int lane = tid & 31;
    const int g    = lane >> 2;
    const int q    = lane & 3;
    const int grp  = lane >> 3;
    const int lrow = lane & 7;
    const int warp_m = (w & 1) * 32;
    const int warp_n = (w >> 1) * 16;
    const int nBlock = blockIdx.x * 64;
    const int mBlock = blockIdx.y * 64;

    const __half* A  = g_oh;
    const __half* Wp = g_wh + (size_t)3 * E_ * E_;

    const int fr0 = tid >> 3,          fc = (tid & 7) * 8;
    const int fr1 = (tid + 256) >> 3;
    const uint32_t ad0 = smem_u32(&Ah[0][fr0][fc]);
    const uint32_t ad1 = smem_u32(&Ah[0][fr1][fc]);
    const uint32_t wd0 = smem_u32(&Wh[0][fr0][fc]);
    const uint32_t wd1 = smem_u32(&Wh[0][fr1][fc]);
    const __half* as0 = A  + (size_t)(mBlock + fr0) * E_ + fc;
    const __half* as1 = A  + (size_t)(mBlock + fr1) * E_ + fc;
    const __half* ws0 = Wp + (size_t)(nBlock + fr0) * E_ + fc;
    const __half* ws1 = Wp + (size_t)(nBlock + fr1) * E_ + fc;

    uint32_t abase[2];
    #pragma unroll
    for (int mt = 0; mt < 2; mt++)
        abase[mt] = smem_u32(&Ah[0][warp_m + mt * 16 + (grp & 1) * 8 + lrow][(grp >> 1) * 8]);
    const uint32_t wbase = smem_u32(&Wh[0][warp_n + (grp >> 1) * 8 + lrow][(grp & 1) * 8]);

    float acc[2][2][4];
    #pragma unroll
    for (int mt = 0; mt < 2; mt++)
        #pragma unroll
        for (int nt = 0; nt < 2; nt++)
            #pragma unroll
            for (int j = 0; j < 4; j++) acc[mt][nt][j] = 0.f;

    CP16(ad0, as0); CP16(ad1, as1);
    CP16(wd0, ws0); CP16(wd1, ws1);
    CP_COMMIT();

    #pragma unroll
    for (int kt = 0; kt < E_ / GK; kt++) {
        const uint32_t cur = (kt & 1) * GBUF;
        CP_WAIT0();
        __syncthreads();
        if (kt + 1 < E_ / GK) {
            const int k0n = (kt + 1) * GK;
            const uint32_t nb = ((kt + 1) & 1) * GBUF;
            CP16(ad0 + nb, as0 + k0n); CP16(ad1 + nb, as1 + k0n);
            CP16(wd0 + nb, ws0 + k0n); CP16(wd1 + nb, ws1 + k0n);
            CP_COMMIT();
        }
        #pragma unroll
        for (int ks = 0; ks < GK / 16; ks++) {
            uint32_t af[2][4];
            #pragma unroll
            for (int mt = 0; mt < 2; mt++)
                LDMX4(af[mt][0], af[mt][1], af[mt][2], af[mt][3],
                      abase[mt] + cur + ks * 32);
            uint32_t b0, b1, b2, b3;
            LDMX4(b0, b1, b2, b3, wbase + cur + ks * 32);
            #pragma unroll
            for (int mt = 0; mt < 2; mt++) {
                mma_f16(acc[mt][0], af[mt], b0, b1);
                mma_f16(acc[mt][1], af[mt], b2, b3);
            }
        }
    }

    #pragma unroll
    for (int mt = 0; mt < 2; mt++) {
        int row0 = mBlock + warp_m + mt * 16 + g;
        #pragma unroll
        for (int nt = 0; nt < 2; nt++) {
            int e = nBlock + warp_n + nt * 8 + 2 * q;
            float be0 = bo[e], be1 = bo[e + 1];
            *(float2*)&out[(size_t)row0 * E_ + e] =
                make_float2(acc[mt][nt][0] + be0, acc[mt][nt][1] + be1);
            *(float2*)&out[(size_t)(row0 + 8) * E_ + e] =
                make_float2(acc[mt][nt][2] + be0, acc[mt][nt][3] + be1);
        }
    }
}

// ---------------------------------------------------------------------------
// fp16 attention (byte-identical to the proven R10 version): CTA 128 thr =
// 4 warps; warp owns 32 q-rows. f16 S accumulate + in-place ex2, ones-column
// row sums, single-sync cp.async double buffer.
// ---------------------------------------------------------------------------
#define BC 64
#define KVS 40

__global__ __launch_bounds__(128)
void attn_h16()
{
    __shared__ __half Ks[2][BC][KVS];
    __shared__ __half Vs[2][BC][KVS];

    const int tid  = threadIdx.x;
    const int w    = tid >> 5;
    const int lane = tid & 31;
    const int g    = lane >> 2;
    const int q    = lane & 3;
    const int grp  = lane >> 3;
    const int lrow = lane & 7;
    const int bh   = blockIdx.y;
    const int qt   = blockIdx.x;

    const __half* Qw = g_q + ((size_t)bh * N_ + qt * 128 + w * 32) * D_;
    const __half* Kp = g_k + (size_t)bh * N_ * D_;
    const __half* Vp = g_v + (size_t)bh * N_ * D_;

    uint32_t qa[2][2][4];
    #pragma unroll
    for (int mt = 0; mt < 2; mt++) {
        #pragma unroll
        for (int ks = 0; ks < 2; ks++) {
            const __half* r0 = Qw + (mt * 16 + g    ) * D_ + ks * 16;
            const __half* r8 = Qw + (mt * 16 + g + 8) * D_ + ks * 16;
            qa[mt][ks][0] = *(const uint32_t*)&r0[2 * q    ];
            qa[mt][ks][1] = *(const uint32_t*)&r8[2 * q    ];
            qa[mt][ks][2] = *(const uint32_t*)&r0[2 * q + 8];
            qa[mt][ks][3] = *(const uint32_t*)&r8[2 * q + 8];
        }
    }

    const uint32_t kbase0 = smem_u32(&Ks[0][(grp >> 1) * 8 + lrow][(grp & 1) * 8]);
    const uint32_t vbase0 = smem_u32(&Vs[0][(grp & 1) * 8 + lrow][(grp >> 1) * 8]);
    const uint32_t bufstep = BC * KVS * 2;

    const int r0c = tid >> 2,         h0c = (tid & 3) * 8;
    const int r1c = (tid + 128) >> 2, h1c = h0c;
    const uint32_t kd0 = smem_u32(&Ks[0][r0c][h0c]);
    const uint32_t kd1 = smem_u32(&Ks[0][r1c][h1c]);
    const uint32_t vd0 = smem_u32(&Vs[0][r0c][h0c]);
    const uint32_t vd1 = smem_u32(&Vs[0][r1c][h1c]);

    float o[2][4][4];
    #pragma unroll
    for (int mt = 0; mt < 2; mt++)
        #pragma unroll
        for (int i = 0; i < 4; i++)
            #pragma unroll
            for (int j = 0; j < 4; j++) o[mt][i][j] = 0.f;
    float lsum[2][4] = {{0.f,0.f,0.f,0.f},{0.f,0.f,0.f,0.f}};
    const uint32_t ones = (g == 0) ? 0x3C003C00u : 0u;

    CP16(kd0, Kp + (size_t)r0c * D_ + h0c);
    CP16(kd1, Kp + (size_t)r1c * D_ + h1c);
    CP16(vd0, Vp + (size_t)r0c * D_ + h0c);
    CP16(vd1, Vp + (size_t)r1c * D_ + h1c);
    CP_COMMIT();

    for (int kt = 0; kt < N_ / BC; kt++) {
        const uint32_t cur = (kt & 1) * bufstep;
        CP_WAIT0();
        __syncthreads();
        if (kt + 1 < N_ / BC) {
            const uint32_t nb = ((kt + 1) & 1) * bufstep;
            const size_t base = (size_t)(kt + 1) * BC;
            CP16(kd0 + nb, Kp + (base + r0c) * D_ + h0c);
            CP16(kd1 + nb, Kp + (base + r1c) * D_ + h1c);
            CP16(vd0 + nb, Vp + (base + r0c) * D_ + h0c);
            CP16(vd1 + nb, Vp + (base + r1c) * D_ + h1c);
            CP_COMMIT();
        }

        uint32_t s16[2][8][2];
        #pragma unroll
        for (int mt = 0; mt < 2; mt++)
            #pragma unroll
            for (int nt = 0; nt < 8; nt++) s16[mt][nt][0] = s16[mt][nt][1] = 0u;
        #pragma unroll
        for (int ntp = 0; ntp < 4; ntp++) {
            #pragma unroll
            for (int ks = 0; ks < 2; ks++) {
                uint32_t b0, b1, b2, b3;
                LDMX4(b0, b1, b2, b3, kbase0 + cur + ntp * 16 * (KVS * 2) + ks * 32);
                #pragma unroll
                for (int mt = 0; mt < 2; mt++) {
                    mma_f16c16(s16[mt][2 * ntp    ], qa[mt][ks], b0, b1);
                    mma_f16c16(s16[mt][2 * ntp + 1], qa[mt][ks], b2, b3);
                }
            }
        }

        #pragma unroll
        for (int mt = 0; mt < 2; mt++)
            #pragma unroll
            for (int nt = 0; nt < 8; nt++) {
                s16[mt][nt][0] = ex2h2(s16[mt][nt][0]);
                s16[mt][nt][1] = ex2h2(s16[mt][nt][1]);
            }

        #pragma unroll
        for (int ks = 0; ks < 4; ks++) {
            uint32_t aP[2][4];
            #pragma unroll
            for (int mt = 0; mt < 2; mt++) {
                aP[mt][0] = s16[mt][2*ks][0];   aP[mt][1] = s16[mt][2*ks][1];
                aP[mt][2] = s16[mt][2*ks+1][0]; aP[mt][3] = s16[mt][2*ks+1][1];
            }
            #pragma unroll
            for (int ntp = 0; ntp < 2; ntp++) {
                uint32_t b0, b1, b2, b3;
                LDMX4T(b0, b1, b2, b3, vbase0 + cur + ks * 16 * (KVS * 2) + ntp * 32);
                #pragma unroll
                for (int mt = 0; mt < 2; mt++) {
                    mma_f16(o[mt][2 * ntp    ], aP[mt], b0, b1);
                    mma_f16(o[mt][2 * ntp + 1], aP[mt], b2, b3);
                }
            }
            mma_f16(lsum[0], aP[0], ones, ones);
            mma_f16(lsum[1], aP[1], ones, ones);
        }
    }

    const int srcl = lane & ~3;
    const int b = bh >> 3, h = bh & 7;
    #pragma unroll
    for (int mt = 0; mt < 2; mt++) {
        const float inv0 = 1.f / __shfl_sync(0xffffffffu, lsum[mt][0], srcl);
        const float inv1 = 1.f / __shfl_sync(0xffffffffu, lsum[mt][2], srcl);
        const int row0 = qt * 128 + w * 32 + mt * 16 + g;
        __half* dst0 = g_oh + ((size_t)(b * N_ + row0    )) * E_ + h * D_;
        __half* dst1 = g_oh + ((size_t)(b * N_ + row0 + 8)) * E_ + h * D_;
        #pragma unroll
        for (int nt = 0; nt < 4; nt++) {
            int cc = nt * 8 + 2 * q;
            *(__half2*)&dst0[cc] = __floats2half2_rn(o[mt][nt][0] * inv0, o[mt][nt][1] * inv0);
            *(__half2*)&dst1[cc] = __floats2half2_rn(o[mt][nt][2] * inv1, o[mt][nt][3] * inv1);
        }
    }
}

// ---------------------------------------------------------------------------
extern "C" void kernel_launch(void* const* d_in, const int* in_sizes, int n_in,
                              void* d_out, int out_size)
{
    const float* x  = (const float*)d_in[0];
    const float* Wq = (const float*)d_in[1];
    const float* bq = (const float*)d_in[2];
    const float* Wk = (const float*)d_in[3];
    const float* bk = (const float*)d_in[4];
    const float* Wv = (const float*)d_in[5];
    const float* bv = (const float*)d_in[6];
    const float* Wo = (const float*)d_in[7];
    const float* bo = (const float*)d_in[8];
    float* out = (float*)d_out;

    convert_kernel<<<2304, 256>>>(x, Wq, Wk, Wv, Wo);
    gemm_qkv<<<dim3(12, 128), 256>>>(bq, bk, bv);
    attn_h16<<<dim3(N_ / 128, B_ * H_), 128>>>();
    gemm_out<<<dim3(4, 128), 256>>>(bo, out);
}